// round 6
// baseline (speedup 1.0000x reference)
#include <cuda_runtime.h>

#define BB 1024
#define DD 128
#define TT 256
#define HH 64
#define GG 256  // 4*H

typedef unsigned long long ull;

__device__ float g_xp0[(size_t)BB * TT * GG];

__device__ __forceinline__ void ffma2(ull& d, ull a, ull b) {
    asm("fma.rn.f32x2 %0, %1, %2, %0;" : "+l"(d) : "l"(a), "l"(b));
}
__device__ __forceinline__ float2 u2f(ull u) {
    float2 r;
    r.x = __uint_as_float((unsigned)(u & 0xffffffffULL));
    r.y = __uint_as_float((unsigned)(u >> 32));
    return r;
}

__device__ __forceinline__ float sigm(float x) {
    return __fdividef(1.0f, 1.0f + __expf(-x));
}
__device__ __forceinline__ float tanh_acc(float x) {
    float a = fabsf(x);
    float e = __expf(-2.0f * a);
    float r = (1.0f - e) * __fdividef(1.0f, 1.0f + e);
    return copysignf(r, x);
}

// ---------------------------------------------------------------------------
// Kernel 1 (reverted to R3-winning version)
// ---------------------------------------------------------------------------
__global__ __launch_bounds__(256) void k_inproj(
    const float* __restrict__ x,
    const float* __restrict__ w_ih0,
    const float* __restrict__ b_ih0,
    const float* __restrict__ b_hh0)
{
    extern __shared__ float sm[];
    float* wt = sm;              // [128][260]
    float* xd = sm + 128 * 260;  // [128][64] of float2 {v, v}

    const int tid = threadIdx.x;
    const int b   = blockIdx.x;

    {
        const float4* w4 = (const float4*)w_ih0;
        #pragma unroll
        for (int i = 0; i < 32; i++) {
            int j  = tid + i * 256;
            int g  = j >> 5;
            int dq = j & 31;
            float4 v = w4[j];
            wt[(4 * dq + 0) * 260 + g] = v.x;
            wt[(4 * dq + 1) * 260 + g] = v.y;
            wt[(4 * dq + 2) * 260 + g] = v.z;
            wt[(4 * dq + 3) * 260 + g] = v.w;
        }
    }

    const int tx = tid & 31;
    const int ty = tid >> 5;

    const float4* bi4 = (const float4*)b_ih0;
    const float4* bh4 = (const float4*)b_hh0;
    float4 bia = bi4[tx],      bha = bh4[tx];
    float4 bib = bi4[32 + tx], bhb = bh4[32 + tx];
    float blo[4] = {bia.x + bha.x, bia.y + bha.y, bia.z + bha.z, bia.w + bha.w};
    float bhi[4] = {bib.x + bhb.x, bib.y + bhb.y, bib.z + bhb.z, bib.w + bhb.w};

    for (int tt = 0; tt < 4; tt++) {
        const int t0 = tt * 64;
        __syncthreads();
        {
            const float* xb = x + (size_t)b * DD * TT + t0;
            int t = tid & 63, d0 = tid >> 6;
            #pragma unroll
            for (int d = d0; d < 128; d += 4) {
                float v = xb[d * TT + t];
                ((float2*)xd)[d * 64 + t] = make_float2(v, v);
            }
        }
        __syncthreads();

        ull acc[8][4];
        #pragma unroll
        for (int a = 0; a < 8; a++)
            #pragma unroll
            for (int e = 0; e < 4; e++) acc[a][e] = 0ULL;

        #pragma unroll 4
        for (int d = 0; d < 128; d++) {
            ulonglong2 x01 = *(const ulonglong2*)&xd[(d * 64 + ty * 4) * 2];
            ulonglong2 x23 = *(const ulonglong2*)&xd[(d * 64 + ty * 4 + 2) * 2];
            ulonglong2 x45 = *(const ulonglong2*)&xd[(d * 64 + 32 + ty * 4) * 2];
            ulonglong2 x67 = *(const ulonglong2*)&xd[(d * 64 + 32 + ty * 4 + 2) * 2];
            ulonglong2 wa = *(const ulonglong2*)&wt[d * 260 + tx * 4];
            ulonglong2 wb = *(const ulonglong2*)&wt[d * 260 + 128 + tx * 4];
            ull xv[8] = {x01.x, x01.y, x23.x, x23.y, x45.x, x45.y, x67.x, x67.y};
            ull wp[4] = {wa.x, wa.y, wb.x, wb.y};
            #pragma unroll
            for (int a = 0; a < 8; a++)
                #pragma unroll
                for (int e = 0; e < 4; e++)
                    ffma2(acc[a][e], xv[a], wp[e]);
        }

        #pragma unroll
        for (int a = 0; a < 8; a++) {
            int t = (a < 4) ? (ty * 4 + a) : (32 + ty * 4 + (a - 4));
            float* row = g_xp0 + ((size_t)b * TT + t0 + t) * GG;
            float2 p0 = u2f(acc[a][0]), p1 = u2f(acc[a][1]);
            float2 p2 = u2f(acc[a][2]), p3 = u2f(acc[a][3]);
            float4 lo = make_float4(p0.x + blo[0], p0.y + blo[1],
                                    p1.x + blo[2], p1.y + blo[3]);
            float4 hi = make_float4(p2.x + bhi[0], p2.y + bhi[1],
                                    p3.x + bhi[2], p3.y + bhi[3]);
            *(float4*)(row + tx * 4)       = lo;
            *(float4*)(row + 128 + tx * 4) = hi;
        }
    }
}

// ---------------------------------------------------------------------------
// Kernel 2: layer-pipelined fused LSTM — 2 barriers/step.
// Period p computes gates0(p+1) AND gates1(p) in one phase, then both updates.
// ---------------------------------------------------------------------------
#define W0OFF 0
#define W1OFF 16384
#define W2OFF 32768
#define H0OFF 49152
#define H1OFF 49664
#define GS0OFF 50176
#define GS1OFF 52480
#define SMFL   54784

__device__ __forceinline__ void cell_upd(const float* __restrict__ gsm,
                                         float* __restrict__ hs,
                                         int cb, int ch, float& ca, float& cbv)
{
    float i0 = gsm[ch * 9 + cb],         f0 = gsm[(64 + ch) * 9 + cb];
    float g0 = gsm[(128 + ch) * 9 + cb], o0 = gsm[(192 + ch) * 9 + cb];
    float i1 = gsm[ch * 9 + cb + 4],         f1 = gsm[(64 + ch) * 9 + cb + 4];
    float g1 = gsm[(128 + ch) * 9 + cb + 4], o1 = gsm[(192 + ch) * 9 + cb + 4];
    ca  = sigm(f0) * ca  + sigm(i0) * tanh_acc(g0);
    cbv = sigm(f1) * cbv + sigm(i1) * tanh_acc(g1);
    hs[cb * 64 + ch]       = sigm(o0) * tanh_acc(ca);
    hs[(cb + 4) * 64 + ch] = sigm(o1) * tanh_acc(cbv);
}

__global__ __launch_bounds__(256) void k_lstm(
    const float* __restrict__ w_hh0,
    const float* __restrict__ w_ih1,
    const float* __restrict__ b_ih1,
    const float* __restrict__ b_hh1,
    const float* __restrict__ w_hh1,
    const float* __restrict__ w_fc,
    const float* __restrict__ b_fc,
    float* __restrict__ out)
{
    extern __shared__ float sm[];
    float* w0q = sm + W0OFF;
    float* w1q = sm + W1OFF;
    float* w2q = sm + W2OFF;
    float* h0f = sm + H0OFF;
    float* h1f = sm + H1OFF;
    float* gs0 = sm + GS0OFF;
    float* gs1 = sm + GS1OFF;

    const int tid = threadIdx.x;
    const int b0  = blockIdx.x * 8;

    {
        const float4* a4 = (const float4*)w_hh0;
        const float4* b4 = (const float4*)w_ih1;
        const float4* c4 = (const float4*)w_hh1;
        #pragma unroll
        for (int i = 0; i < 16; i++) {
            int j  = tid + i * 256;
            int g  = j >> 4;
            int k4 = j & 15;
            ((float4*)w0q)[k4 * 256 + g] = a4[j];
            ((float4*)w1q)[k4 * 256 + g] = b4[j];
            ((float4*)w2q)[k4 * 256 + g] = c4[j];
        }
    }
    for (int i = tid; i < 512; i += 256) { h0f[i] = 0.0f; h1f[i] = 0.0f; }

    const float bias1 = b_ih1[tid] + b_hh1[tid];
    const int ch = tid & 63;
    const int cb = tid >> 6;
    float c0a = 0.0f, c0b = 0.0f, c1a = 0.0f, c1b = 0.0f;

    const float* xp = g_xp0 + (size_t)b0 * TT * GG + tid;

    float xv[8];
    #pragma unroll
    for (int b = 0; b < 8; b++) xv[b] = xp[(size_t)b * TT * GG];  // xp(0)

    __syncthreads();

    // pre-step: gates0(0) = xp(0)
    #pragma unroll
    for (int b = 0; b < 8; b++) gs0[tid * 9 + b] = xv[b];
    #pragma unroll
    for (int b = 0; b < 8; b++)
        xv[b] = xp[((size_t)b * TT + 1) * GG];  // prefetch xp(1)
    __syncthreads();
    cell_upd(gs0, h0f, cb, ch, c0a, c0b);       // -> h0(0)
    __syncthreads();

    for (int p = 0; p < 255; p++) {
        {   // A-GEMM: gates0(p+1)
            ull acc[8];
            #pragma unroll
            for (int b = 0; b < 8; b++) acc[b] = 0ULL;
            #pragma unroll
            for (int k4 = 0; k4 < 16; k4++) {
                ulonglong2 w = *(const ulonglong2*)&w0q[k4 * 1024 + tid * 4];
                #pragma unroll
                for (int b = 0; b < 8; b++) {
                    ulonglong2 h = *(const ulonglong2*)&h0f[b * 64 + k4 * 4];
                    ffma2(acc[b], h.x, w.x);
                    ffma2(acc[b], h.y, w.y);
                }
            }
            #pragma unroll
            for (int b = 0; b < 8; b++) {
                float2 s = u2f(acc[b]);
                gs0[tid * 9 + b] = xv[b] + s.x + s.y;
            }
        }
        {   // prefetch xp(p+2), lands under C-GEMM
            int tn = (p + 2 < TT) ? p + 2 : TT - 1;
            #pragma unroll
            for (int b = 0; b < 8; b++)
                xv[b] = xp[((size_t)b * TT + tn) * GG];
        }
        {   // C-GEMM: gates1(p)
            ull acc[8];
            #pragma unroll
            for (int b = 0; b < 8; b++) acc[b] = 0ULL;
            #pragma unroll
            for (int k4 = 0; k4 < 16; k4++) {
                ulonglong2 wa = *(const ulonglong2*)&w1q[k4 * 1024 + tid * 4];
                ulonglong2 wb = *(const ulonglong2*)&w2q[k4 * 1024 + tid * 4];
                #pragma unroll
                for (int b = 0; b < 8; b++) {
                    ulonglong2 ha = *(const ulonglong2*)&h0f[b * 64 + k4 * 4];
                    ulonglong2 hb = *(const ulonglong2*)&h1f[b * 64 + k4 * 4];
                    ffma2(acc[b], ha.x, wa.x);
                    ffma2(acc[b], ha.y, wa.y);
                    ffma2(acc[b], hb.x, wb.x);
                    ffma2(acc[b], hb.y, wb.y);
                }
            }
            #pragma unroll
            for (int b = 0; b < 8; b++) {
                float2 s = u2f(acc[b]);
                gs1[tid * 9 + b] = bias1 + s.x + s.y;
            }
        }
        __syncthreads();  // (1)
        cell_upd(gs0, h0f, cb, ch, c0a, c0b);   // -> h0(p+1)
        cell_upd(gs1, h1f, cb, ch, c1a, c1b);   // -> h1(p)
        __syncthreads();  // (2)
    }

    {   // epilogue: gates1(255)
        ull acc[8];
        #pragma unroll
        for (int b = 0; b < 8; b++) acc[b] = 0ULL;
        #pragma unroll
        for (int k4 = 0; k4 < 16; k4++) {
            ulonglong2 wa = *(const ulonglong2*)&w1q[k4 * 1024 + tid * 4];
            ulonglong2 wb = *(const ulonglong2*)&w2q[k4 * 1024 + tid * 4];
            #pragma unroll
            for (int b = 0; b < 8; b++) {
                ulonglong2 ha = *(const ulonglong2*)&h0f[b * 64 + k4 * 4];
                ulonglong2 hb = *(const ulonglong2*)&h1f[b * 64 + k4 * 4];
                ffma2(acc[b], ha.x, wa.x);
                ffma2(acc[b], ha.y, wa.y);
                ffma2(acc[b], hb.x, wb.x);
                ffma2(acc[b], hb.y, wb.y);
            }
        }
        #pragma unroll
        for (int b = 0; b < 8; b++) {
            float2 s = u2f(acc[b]);
            gs1[tid * 9 + b] = bias1 + s.x + s.y;
        }
    }
    __syncthreads();
    cell_upd(gs1, h1f, cb, ch, c1a, c1b);       // -> h1(255)
    __syncthreads();

    // Head: scores[b, :] = hT @ w_fc^T + b_fc
    float* wfct = w0q;  // reuse: [k][o], 64x128
    for (int i = tid; i < 128 * 64; i += 256) {
        int o = i >> 6, k = i & 63;
        wfct[k * 128 + o] = w_fc[i];
    }
    __syncthreads();

    #pragma unroll
    for (int q = 0; q < 4; q++) {
        int p  = tid + q * 256;
        int bo = p >> 7;
        int o  = p & 127;
        float acc = b_fc[o];
        #pragma unroll 4
        for (int k = 0; k < 64; k++)
            acc += h1f[bo * 64 + k] * wfct[k * 128 + o];
        out[(size_t)(b0 + bo) * 128 + o] = acc;
    }
}

extern "C" void kernel_launch(void* const* d_in, const int* in_sizes, int n_in,
                              void* d_out, int out_size)
{
    const float* x     = (const float*)d_in[0];
    const float* w_ih0 = (const float*)d_in[1];
    const float* w_hh0 = (const float*)d_in[2];
    const float* b_ih0 = (const float*)d_in[3];
    const float* b_hh0 = (const float*)d_in[4];
    const float* w_ih1 = (const float*)d_in[5];
    const float* w_hh1 = (const float*)d_in[6];
    const float* b_ih1 = (const float*)d_in[7];
    const float* b_hh1 = (const float*)d_in[8];
    const float* w_fc  = (const float*)d_in[9];
    const float* b_fc  = (const float*)d_in[10];
    float* out = (float*)d_out;

    const int smem1 = (128 * 260 + 128 * 64 * 2) * 4;  // 198656
    const int smem2 = SMFL * 4;                        // 219136

    cudaFuncSetAttribute(k_inproj, cudaFuncAttributeMaxDynamicSharedMemorySize, smem1);
    cudaFuncSetAttribute(k_lstm,   cudaFuncAttributeMaxDynamicSharedMemorySize, smem2);

    k_inproj<<<1024, 256, smem1>>>(x, w_ih0, b_ih0, b_hh0);
    k_lstm<<<128, 256, smem2>>>(w_hh0, w_ih1, b_ih1, b_hh1, w_hh1, w_fc, b_fc, out);
}

// round 10
// speedup vs baseline: 3.5820x; 3.5820x over previous
#include <cuda_runtime.h>

#define BB 1024
#define DD 128
#define TT 256
#define HH 64
#define GG 256  // 4*H

typedef unsigned long long ull;

__device__ float g_xp0[(size_t)BB * TT * GG];

__device__ __forceinline__ void ffma2(ull& d, ull a, ull b) {
    asm("fma.rn.f32x2 %0, %1, %2, %0;" : "+l"(d) : "l"(a), "l"(b));
}
__device__ __forceinline__ float2 u2f(ull u) {
    float2 r;
    r.x = __uint_as_float((unsigned)(u & 0xffffffffULL));
    r.y = __uint_as_float((unsigned)(u >> 32));
    return r;
}

__device__ __forceinline__ float sigm(float x) {
    return __fdividef(1.0f, 1.0f + __expf(-x));
}
__device__ __forceinline__ float tanh_acc(float x) {
    float a = fabsf(x);
    float e = __expf(-2.0f * a);
    float r = (1.0f - e) * __fdividef(1.0f, 1.0f + e);
    return copysignf(r, x);
}

// ---------------------------------------------------------------------------
// Kernel 1: xp0[b,t,g] = sum_d x[b,d,t] * w_ih0[g,d] + bias[g]
// (byte-identical to the R3 winner; ~455us)
// ---------------------------------------------------------------------------
__global__ __launch_bounds__(256) void k_inproj(
    const float* __restrict__ x,
    const float* __restrict__ w_ih0,
    const float* __restrict__ b_ih0,
    const float* __restrict__ b_hh0)
{
    extern __shared__ float sm[];
    float* wt = sm;              // [128][260]
    float* xd = sm + 128 * 260;  // [128][64] of float2 {v, v}

    const int tid = threadIdx.x;
    const int b   = blockIdx.x;

    {
        const float4* w4 = (const float4*)w_ih0;
        #pragma unroll
        for (int i = 0; i < 32; i++) {
            int j  = tid + i * 256;
            int g  = j >> 5;
            int dq = j & 31;
            float4 v = w4[j];
            wt[(4 * dq + 0) * 260 + g] = v.x;
            wt[(4 * dq + 1) * 260 + g] = v.y;
            wt[(4 * dq + 2) * 260 + g] = v.z;
            wt[(4 * dq + 3) * 260 + g] = v.w;
        }
    }

    const int tx = tid & 31;
    const int ty = tid >> 5;

    const float4* bi4 = (const float4*)b_ih0;
    const float4* bh4 = (const float4*)b_hh0;
    float4 bia = bi4[tx],      bha = bh4[tx];
    float4 bib = bi4[32 + tx], bhb = bh4[32 + tx];
    float blo[4] = {bia.x + bha.x, bia.y + bha.y, bia.z + bha.z, bia.w + bha.w};
    float bhi[4] = {bib.x + bhb.x, bib.y + bhb.y, bib.z + bhb.z, bib.w + bhb.w};

    for (int tt = 0; tt < 4; tt++) {
        const int t0 = tt * 64;
        __syncthreads();
        {
            const float* xb = x + (size_t)b * DD * TT + t0;
            int t = tid & 63, d0 = tid >> 6;
            #pragma unroll
            for (int d = d0; d < 128; d += 4) {
                float v = xb[d * TT + t];
                ((float2*)xd)[d * 64 + t] = make_float2(v, v);
            }
        }
        __syncthreads();

        ull acc[8][4];
        #pragma unroll
        for (int a = 0; a < 8; a++)
            #pragma unroll
            for (int e = 0; e < 4; e++) acc[a][e] = 0ULL;

        #pragma unroll 4
        for (int d = 0; d < 128; d++) {
            ulonglong2 x01 = *(const ulonglong2*)&xd[(d * 64 + ty * 4) * 2];
            ulonglong2 x23 = *(const ulonglong2*)&xd[(d * 64 + ty * 4 + 2) * 2];
            ulonglong2 x45 = *(const ulonglong2*)&xd[(d * 64 + 32 + ty * 4) * 2];
            ulonglong2 x67 = *(const ulonglong2*)&xd[(d * 64 + 32 + ty * 4 + 2) * 2];
            ulonglong2 wa = *(const ulonglong2*)&wt[d * 260 + tx * 4];
            ulonglong2 wb = *(const ulonglong2*)&wt[d * 260 + 128 + tx * 4];
            ull xv[8] = {x01.x, x01.y, x23.x, x23.y, x45.x, x45.y, x67.x, x67.y};
            ull wp[4] = {wa.x, wa.y, wb.x, wb.y};
            #pragma unroll
            for (int a = 0; a < 8; a++)
                #pragma unroll
                for (int e = 0; e < 4; e++)
                    ffma2(acc[a][e], xv[a], wp[e]);
        }

        #pragma unroll
        for (int a = 0; a < 8; a++) {
            int t = (a < 4) ? (ty * 4 + a) : (32 + ty * 4 + (a - 4));
            float* row = g_xp0 + ((size_t)b * TT + t0 + t) * GG;
            float2 p0 = u2f(acc[a][0]), p1 = u2f(acc[a][1]);
            float2 p2 = u2f(acc[a][2]), p3 = u2f(acc[a][3]);
            float4 lo = make_float4(p0.x + blo[0], p0.y + blo[1],
                                    p1.x + blo[2], p1.y + blo[3]);
            float4 hi = make_float4(p2.x + bhi[0], p2.y + bhi[1],
                                    p3.x + bhi[2], p3.y + bhi[3]);
            *(float4*)(row + tx * 4)       = lo;
            *(float4*)(row + 128 + tx * 4) = hi;
        }
    }
}

// ---------------------------------------------------------------------------
// Kernel 2: layer-pipelined fused LSTM, 2 barriers/step.
// Anti-spill: k4 GEMM loops use partial unroll (2) to bound ptxas's
// load-pipelining window; xp prefetch sits after the C-GEMM store.
// __launch_bounds__(256,1): 1 CTA/SM is already forced by 219KB smem; give
// ptxas the full register budget explicitly.
// ---------------------------------------------------------------------------
#define W0OFF 0
#define W1OFF 16384
#define W2OFF 32768
#define H0OFF 49152
#define H1OFF 49664
#define GS0OFF 50176
#define GS1OFF 52480
#define SMFL   54784

__device__ __forceinline__ void cell_upd(const float* __restrict__ gsm,
                                         float* __restrict__ hs,
                                         int cb, int ch, float& ca, float& cbv)
{
    float i0 = gsm[ch * 9 + cb],         f0 = gsm[(64 + ch) * 9 + cb];
    float g0 = gsm[(128 + ch) * 9 + cb], o0 = gsm[(192 + ch) * 9 + cb];
    float i1 = gsm[ch * 9 + cb + 4],         f1 = gsm[(64 + ch) * 9 + cb + 4];
    float g1 = gsm[(128 + ch) * 9 + cb + 4], o1 = gsm[(192 + ch) * 9 + cb + 4];
    ca  = sigm(f0) * ca  + sigm(i0) * tanh_acc(g0);
    cbv = sigm(f1) * cbv + sigm(i1) * tanh_acc(g1);
    hs[cb * 64 + ch]       = sigm(o0) * tanh_acc(ca);
    hs[(cb + 4) * 64 + ch] = sigm(o1) * tanh_acc(cbv);
}

__global__ __launch_bounds__(256, 1) void k_lstm(
    const float* __restrict__ w_hh0,
    const float* __restrict__ w_ih1,
    const float* __restrict__ b_ih1,
    const float* __restrict__ b_hh1,
    const float* __restrict__ w_hh1,
    const float* __restrict__ w_fc,
    const float* __restrict__ b_fc,
    float* __restrict__ out)
{
    extern __shared__ float sm[];
    float* w0q = sm + W0OFF;
    float* w1q = sm + W1OFF;
    float* w2q = sm + W2OFF;
    float* h0f = sm + H0OFF;
    float* h1f = sm + H1OFF;
    float* gs0 = sm + GS0OFF;
    float* gs1 = sm + GS1OFF;

    const int tid = threadIdx.x;
    const int b0  = blockIdx.x * 8;

    {
        const float4* a4 = (const float4*)w_hh0;
        const float4* b4 = (const float4*)w_ih1;
        const float4* c4 = (const float4*)w_hh1;
        #pragma unroll
        for (int i = 0; i < 16; i++) {
            int j  = tid + i * 256;
            int g  = j >> 4;
            int k4 = j & 15;
            ((float4*)w0q)[k4 * 256 + g] = a4[j];
            ((float4*)w1q)[k4 * 256 + g] = b4[j];
            ((float4*)w2q)[k4 * 256 + g] = c4[j];
        }
    }
    for (int i = tid; i < 512; i += 256) { h0f[i] = 0.0f; h1f[i] = 0.0f; }

    const float bias1 = b_ih1[tid] + b_hh1[tid];
    const int ch = tid & 63;
    const int cb = tid >> 6;
    float c0a = 0.0f, c0b = 0.0f, c1a = 0.0f, c1b = 0.0f;

    const float* xp = g_xp0 + (size_t)b0 * TT * GG + tid;

    float xv[8];
    #pragma unroll
    for (int b = 0; b < 8; b++) xv[b] = xp[(size_t)b * TT * GG];  // xp(0)

    __syncthreads();

    // pre-step: gates0(0) = xp(0)  (h0(-1) = 0)
    #pragma unroll
    for (int b = 0; b < 8; b++) gs0[tid * 9 + b] = xv[b];
    #pragma unroll
    for (int b = 0; b < 8; b++)
        xv[b] = xp[((size_t)b * TT + 1) * GG];  // prefetch xp(1)
    __syncthreads();
    cell_upd(gs0, h0f, cb, ch, c0a, c0b);       // -> h0(0)
    __syncthreads();

    for (int p = 0; p < 255; p++) {
        {   // A-GEMM: gates0(p+1) = xp(p+1) + h0(p) @ w_hh0^T
            ull acc[8];
            #pragma unroll
            for (int b = 0; b < 8; b++) acc[b] = 0ULL;
            #pragma unroll 2
            for (int k4 = 0; k4 < 16; k4++) {
                ulonglong2 w = *(const ulonglong2*)&w0q[k4 * 1024 + tid * 4];
                #pragma unroll
                for (int b = 0; b < 8; b++) {
                    ulonglong2 h = *(const ulonglong2*)&h0f[b * 64 + k4 * 4];
                    ffma2(acc[b], h.x, w.x);
                    ffma2(acc[b], h.y, w.y);
                }
            }
            #pragma unroll
            for (int b = 0; b < 8; b++) {
                float2 s = u2f(acc[b]);
                gs0[tid * 9 + b] = xv[b] + s.x + s.y;
            }
        }
        {   // C-GEMM: gates1(p) = bias1 + h0(p) @ w_ih1^T + h1(p-1) @ w_hh1^T
            ull acc[8];
            #pragma unroll
            for (int b = 0; b < 8; b++) acc[b] = 0ULL;
            #pragma unroll 2
            for (int k4 = 0; k4 < 16; k4++) {
                ulonglong2 wa = *(const ulonglong2*)&w1q[k4 * 1024 + tid * 4];
                ulonglong2 wb = *(const ulonglong2*)&w2q[k4 * 1024 + tid * 4];
                #pragma unroll
                for (int b = 0; b < 8; b++) {
                    ulonglong2 ha = *(const ulonglong2*)&h0f[b * 64 + k4 * 4];
                    ulonglong2 hb = *(const ulonglong2*)&h1f[b * 64 + k4 * 4];
                    ffma2(acc[b], ha.x, wa.x);
                    ffma2(acc[b], ha.y, wa.y);
                    ffma2(acc[b], hb.x, wb.x);
                    ffma2(acc[b], hb.y, wb.y);
                }
            }
            #pragma unroll
            for (int b = 0; b < 8; b++) {
                float2 s = u2f(acc[b]);
                gs1[tid * 9 + b] = bias1 + s.x + s.y;
            }
        }
        {   // prefetch xp(p+2): after GEMMs, short live range into next A
            int tn = (p + 2 < TT) ? p + 2 : TT - 1;
            #pragma unroll
            for (int b = 0; b < 8; b++)
                xv[b] = xp[((size_t)b * TT + tn) * GG];
        }
        __syncthreads();  // (1)
        cell_upd(gs0, h0f, cb, ch, c0a, c0b);   // -> h0(p+1)
        cell_upd(gs1, h1f, cb, ch, c1a, c1b);   // -> h1(p)
        __syncthreads();  // (2)
    }

    {   // epilogue: gates1(255) from h0(255), h1(254)
        ull acc[8];
        #pragma unroll
        for (int b = 0; b < 8; b++) acc[b] = 0ULL;
        #pragma unroll 2
        for (int k4 = 0; k4 < 16; k4++) {
            ulonglong2 wa = *(const ulonglong2*)&w1q[k4 * 1024 + tid * 4];
            ulonglong2 wb = *(const ulonglong2*)&w2q[k4 * 1024 + tid * 4];
            #pragma unroll
            for (int b = 0; b < 8; b++) {
                ulonglong2 ha = *(const ulonglong2*)&h0f[b * 64 + k4 * 4];
                ulonglong2 hb = *(const ulonglong2*)&h1f[b * 64 + k4 * 4];
                ffma2(acc[b], ha.x, wa.x);
                ffma2(acc[b], ha.y, wa.y);
                ffma2(acc[b], hb.x, wb.x);
                ffma2(acc[b], hb.y, wb.y);
            }
        }
        #pragma unroll
        for (int b = 0; b < 8; b++) {
            float2 s = u2f(acc[b]);
            gs1[tid * 9 + b] = bias1 + s.x + s.y;
        }
    }
    __syncthreads();
    cell_upd(gs1, h1f, cb, ch, c1a, c1b);       // -> h1(255)
    __syncthreads();

    // Head: scores[b, :] = hT @ w_fc^T + b_fc
    float* wfct = w0q;  // reuse (fully synced): [k][o], 64x128
    for (int i = tid; i < 128 * 64; i += 256) {
        int o = i >> 6, k = i & 63;
        wfct[k * 128 + o] = w_fc[i];
    }
    __syncthreads();

    #pragma unroll
    for (int q = 0; q < 4; q++) {
        int p  = tid + q * 256;
        int bo = p >> 7;
        int o  = p & 127;
        float acc = b_fc[o];
        #pragma unroll 4
        for (int k = 0; k < 64; k++)
            acc += h1f[bo * 64 + k] * wfct[k * 128 + o];
        out[(size_t)(b0 + bo) * 128 + o] = acc;
    }
}

extern "C" void kernel_launch(void* const* d_in, const int* in_sizes, int n_in,
                              void* d_out, int out_size)
{
    const float* x     = (const float*)d_in[0];
    const float* w_ih0 = (const float*)d_in[1];
    const float* w_hh0 = (const float*)d_in[2];
    const float* b_ih0 = (const float*)d_in[3];
    const float* b_hh0 = (const float*)d_in[4];
    const float* w_ih1 = (const float*)d_in[5];
    const float* w_hh1 = (const float*)d_in[6];
    const float* b_ih1 = (const float*)d_in[7];
    const float* b_hh1 = (const float*)d_in[8];
    const float* w_fc  = (const float*)d_in[9];
    const float* b_fc  = (const float*)d_in[10];
    float* out = (float*)d_out;

    const int smem1 = (128 * 260 + 128 * 64 * 2) * 4;  // 198656
    const int smem2 = SMFL * 4;                        // 219136

    cudaFuncSetAttribute(k_inproj, cudaFuncAttributeMaxDynamicSharedMemorySize, smem1);
    cudaFuncSetAttribute(k_lstm,   cudaFuncAttributeMaxDynamicSharedMemorySize, smem2);

    k_inproj<<<1024, 256, smem1>>>(x, w_ih0, b_ih0, b_hh0);
    k_lstm<<<128, 256, smem2>>>(w_hh0, w_ih1, b_ih1, b_hh1, w_hh1, w_fc, b_fc, out);
}